// round 12
// baseline (speedup 1.0000x reference)
#include <cuda_runtime.h>
#include <math.h>

#define NCLS 20
#define NA 5
#define HH 26
#define WW 26
#define NLOC 3380      // NA*HH*WW
#define NLOCP 3392     // padded row count for V
#define NPAD 4096
#define NW 106         // ceil(NLOC/32)
#define VSTRIDE 128    // words per V row (512B, power of two)
#define BATCH 16
#define NMS_TH 0.45f
#define K2 0.31034482758f   // 0.45/1.45
#define PRE_TH 0.005f
#define FEAT_STRIDE 32.0f

__constant__ float c_biases[10] = {1.08f, 1.19f, 3.42f, 4.41f, 6.63f, 11.38f,
                                   9.42f, 5.11f, 16.62f, 10.52f};

// ---- device scratch (static; no allocations) ----
__device__ float g_x1[BATCH * NLOC], g_y1[BATCH * NLOC];
__device__ float g_x2[BATCH * NLOC], g_y2[BATCH * NLOC];
__device__ float g_ka[BATCH * NLOC], g_score[BATCH * NLOC];
__device__ float4 g_sbox[BATCH * NLOC];          // sorted (x1,y1,x2,y2)
__device__ float g_ska[BATCH * NLOC], g_ss[BATCH * NLOC];
__device__ int g_sidx[BATCH * NLOC];
__device__ unsigned g_alive[BATCH * NW];
// victims matrix: V[b][i][jw] = bitmask of j (rank j > i) suppressed by i.
// valid for jw >= word(i); words < word(i) are never read.
__device__ unsigned g_V[(size_t)BATCH * NLOCP * VSTRIDE];   // ~27.8 MB

// ============ kernel 1: decode (fully parallel) ============
__global__ void decode_kernel(const float* __restrict__ x,
                              const float* __restrict__ im_info,
                              float* __restrict__ out)
{
    const int b = blockIdx.y;
    const int loc = blockIdx.x * 128 + threadIdx.x;
    if (loc >= NLOC) return;

    const float im_h = im_info[0];
    const float im_w = im_info[1];
    const float netw = WW * FEAT_STRIDE;
    const float neth = HH * FEAT_STRIDE;
    const bool cond = (netw / im_w) < (neth / im_h);
    const float new_w = cond ? netw : im_w * neth / im_h;
    const float new_h = cond ? im_h * netw / im_w : neth;

    float* prob = out;
    float* bbox = out + (size_t)BATCH * NLOC * 21;
    const float* xb = x + (size_t)b * 125 * (HH * WW);

    int a = loc / (HH * WW);
    int rem = loc - a * (HH * WW);
    int hh = rem / WW;
    int ww = rem - hh * WW;

    float tx = xb[(2 * a) * 676 + rem];
    float ty = xb[(2 * a + 1) * 676 + rem];
    float tw = xb[(10 + 2 * a) * 676 + rem];
    float th = xb[(11 + 2 * a) * 676 + rem];
    float to = xb[(20 + a) * 676 + rem];

    float obj = 1.0f / (1.0f + expf(-to));

    float cf[NCLS];
    float m = -INFINITY;
#pragma unroll
    for (int c = 0; c < NCLS; c++) {
        cf[c] = xb[(25 + 5 * c + a) * 676 + rem];
        m = fmaxf(m, cf[c]);
    }
    float sum = 0.0f;
#pragma unroll
    for (int c = 0; c < NCLS; c++) {
        cf[c] = expf(cf[c] - m);
        sum += cf[c];
    }
    float inv = obj / sum;
    float* pr = prob + ((size_t)b * NLOC + loc) * 21;
#pragma unroll
    for (int c = 0; c < NCLS; c++) pr[c] = cf[c] * inv;

    float sx = 1.0f / (1.0f + expf(-tx));
    float sy = 1.0f / (1.0f + expf(-ty));
    float bxv = ((float)ww + sx) / (float)WW;
    float byv = ((float)hh + sy) / (float)HH;
    float bwv = c_biases[2 * a] * expf(tw) / (float)WW;
    float bhv = c_biases[2 * a + 1] * expf(th) / (float)HH;

    bxv = (bxv - (netw - new_w) * 0.5f / netw) / (new_w / netw);
    byv = (byv - (neth - new_h) * 0.5f / neth) / (new_h / neth);
    bwv = bwv * (netw / new_w);
    bhv = bhv * (neth / new_h);

    float cx = bxv * im_w, cy = byv * im_h;
    float bw2 = bwv * im_w, bh2 = bhv * im_h;

    float4* bo = (float4*)(bbox + ((size_t)b * NLOC + loc) * 4);
    *bo = make_float4(cx, cy, bw2, bh2);

    float X1 = cx - bw2 * 0.5f, Y1 = cy - bh2 * 0.5f;
    float X2 = cx + bw2 * 0.5f, Y2 = cy + bh2 * 0.5f;
    int gi = b * NLOC + loc;
    g_x1[gi] = X1; g_y1[gi] = Y1;
    g_x2[gi] = X2; g_y2[gi] = Y2;
    g_ka[gi] = K2 * ((X2 - X1) * (Y2 - Y1));
    g_score[gi] = (obj < PRE_TH) ? 0.0f : obj;
}

// ============ kernel 2: per-batch bitonic sort on packed 64-bit keys ============
__global__ void __launch_bounds__(1024, 1)
sort_kernel()
{
    __shared__ unsigned long long skey[NPAD];
    const int b = blockIdx.x;
    const int tid = threadIdx.x;
    const int base = b * NLOC;

    for (int p = tid; p < NLOC; p += 1024) {
        unsigned sb = __float_as_uint(g_score[base + p]);
        skey[p] = ((unsigned long long)sb << 32) | (0xFFFFFFFFu - (unsigned)p);
    }
    for (int p = NLOC + tid; p < NPAD; p += 1024)
        skey[p] = 0ull;
    __syncthreads();

    for (unsigned k = 2; k <= NPAD; k <<= 1) {
        for (unsigned j = k >> 1; j > 0; j >>= 1) {
            for (unsigned i = tid; i < NPAD; i += 1024) {
                unsigned ixj = i ^ j;
                if (ixj > i) {
                    unsigned long long ka = skey[i], kb = skey[ixj];
                    bool dirDesc = ((i & k) == 0);
                    if ((kb > ka) == dirDesc) {
                        skey[i] = kb;
                        skey[ixj] = ka;
                    }
                }
            }
            __syncthreads();
        }
    }

    for (int p = tid; p < NLOC; p += 1024) {
        unsigned long long key = skey[p];
        float sc = __uint_as_float((unsigned)(key >> 32));
        int o = (int)(0xFFFFFFFFu - (unsigned)key);
        g_ss[base + p] = sc;
        g_sidx[base + p] = o;
        g_sbox[base + p] = make_float4(g_x1[base + o], g_y1[base + o],
                                       g_x2[base + o], g_y2[base + o]);
        // dead boxes can never suppress: ka = +INF
        g_ska[base + p] = (sc > 0.0f) ? g_ka[base + o] : INFINITY;
    }
    __syncthreads();
    for (int chunk = 0; chunk < NPAD; chunk += 1024) {
        int p = chunk + tid;
        bool alive = (p < NLOC) && ((skey[p] >> 32) != 0ull);
        unsigned w = __ballot_sync(0xFFFFFFFFu, alive);
        int word = p >> 5;
        if ((tid & 31) == 0 && word < NW)
            g_alive[b * NW + word] = w;
    }
}

// ============ kernel 3: victims matrix, row-major, st.128 stores ============
// warp owns i-word w and a group of 4 j-words; lane = j within jword;
// iterate i, ballot -> V[i][jw]; lane r keeps ballots for i = w*32+r.
__global__ void __launch_bounds__(128, 8)
mat_kernel()
{
    const int w = blockIdx.x;                       // i-word
    const int b = blockIdx.z;
    const int lane = threadIdx.x & 31;
    const int warpid = threadIdx.x >> 5;
    const int jg = blockIdx.y * 4 + warpid;         // j-word group of 4
    const int jw0 = jg * 4;
    if (jw0 >= NW || jw0 + 3 < w) return;

    const int base = b * NLOC;

    float4 jb[4]; float jka[4];
#pragma unroll
    for (int g = 0; g < 4; g++) {
        int jw = jw0 + g;
        int j = jw * 32 + lane;
        if (jw < NW && j < NLOC) {
            jb[g] = g_sbox[base + j];
            jka[g] = g_ska[base + j];
        } else {
            jb[g] = make_float4(0.f, 0.f, 0.f, 0.f);
            jka[g] = INFINITY;
        }
    }

    unsigned vout[4] = {0u, 0u, 0u, 0u};
#pragma unroll 2
    for (int r = 0; r < 32; r++) {
        int i = w * 32 + r;
        int iv = (i < NLOC) ? i : (NLOC - 1);
        float4 ib = __ldg(&g_sbox[base + iv]);
        float ika = (i < NLOC) ? __ldg(&g_ska[base + iv]) : INFINITY;
#pragma unroll
        for (int g = 0; g < 4; g++) {
            int jw = jw0 + g;
            float iw = fminf(ib.z, jb[g].z) - fmaxf(ib.x, jb[g].x);
            float ih = fminf(ib.w, jb[g].w) - fmaxf(ib.y, jb[g].y);
            float inter = fmaxf(iw, 0.0f) * fmaxf(ih, 0.0f);
            bool sup = (inter > ika + jka[g]) &&
                       ((jw > w) || ((jw == w) && (lane > r)));
            unsigned m = __ballot_sync(0xFFFFFFFFu, sup);
            if (lane == r) vout[g] = m;
        }
    }

    size_t row = (size_t)b * NLOCP + (size_t)(w * 32 + lane);
    *((uint4*)&g_V[row * VSTRIDE + jw0]) =
        make_uint4(vout[0], vout[1], vout[2], vout[3]);
}

// ============ kernel 4: exact greedy sweep, one warp per batch ============
#define NPEND 6
__global__ void __launch_bounds__(256, 1)
reduce_kernel(float* __restrict__ out)
{
    __shared__ unsigned s_removed[NW];
    __shared__ unsigned s_kept[NW];
    __shared__ unsigned s_alive[NW];

    const int b = blockIdx.x;
    const int tid = threadIdx.x;
    const int lane = tid & 31;
    const int base = b * NLOC;
    const unsigned* V = g_V + (size_t)b * NLOCP * VSTRIDE;

    for (int w = tid; w < NW; w += 256) {
        s_removed[w] = 0u;
        s_kept[w] = 0u;
        s_alive[w] = g_alive[b * NW + w];
    }
    __syncthreads();

    if (tid < 32) {
        // rolling prefetch registers
        unsigned diag = __ldg(V + (size_t)lane * VSTRIDE + 0);       // word(c)=0
        unsigned specv = __ldg(V + (size_t)lane * VSTRIDE + 1);      // word c+1
        // deferred apply slots (rows kept at previous step)
        unsigned q0[NPEND], q1[NPEND], q2[NPEND], q3[NPEND];
        int pcnt = 0;
#pragma unroll
        for (int p = 0; p < NPEND; p++) { q0[p]=0u; q1[p]=0u; q2[p]=0u; q3[p]=0u; }

        for (int c = 0; c < NW; c++) {
            // prefetch next step's diag/spec (static addresses)
            unsigned dn = 0u, sn = 0u;
            if (c + 1 < NW) {
                const unsigned* NR = V + (size_t)((c + 1) * 32 + lane) * VSTRIDE;
                dn = __ldg(NR + (c + 1));
                if (c + 2 < NW) sn = __ldg(NR + (c + 2));
            }

            // in-word greedy chain (register + shuffle only)
            unsigned cand = s_alive[c] & ~s_removed[c];
            unsigned km = 0u;
            while (cand) {
                int bb = __ffs(cand) - 1;
                km |= 1u << bb;
                unsigned vb = __shfl_sync(0xFFFFFFFFu, diag, bb);
                cand &= ~vb;
                cand &= ~(1u << bb);
            }
            if (lane == 0) s_kept[c] = km;

            // spec path: removed[c+1] gets this step's contribution NOW
            if (c + 1 < NW) {
                unsigned red = __reduce_or_sync(0xFFFFFFFFu,
                                                ((km >> lane) & 1u) ? specv : 0u);
                if (lane == 0) s_removed[c + 1] |= red;
            }

            // consume deferred rows from step c-1 (their loads are long arrived)
            {
                unsigned a0 = 0u, a1 = 0u, a2 = 0u, a3 = 0u;
#pragma unroll
                for (int p = 0; p < NPEND; p++) {
                    a0 |= q0[p]; a1 |= q1[p]; a2 |= q2[p]; a3 |= q3[p];
                }
                if (a0) s_removed[lane] |= a0;
                if (a1) s_removed[lane + 32] |= a1;
                if (a2) s_removed[lane + 64] |= a2;
                if (a3 && lane + 96 < NW) s_removed[lane + 96] |= a3;
            }

            // issue deferred loads for this step's kept rows (words >= c, guarded)
            {
                unsigned kk = km;
                pcnt = 0;
#pragma unroll
                for (int p = 0; p < NPEND; p++) {
                    q0[p] = 0u; q1[p] = 0u; q2[p] = 0u; q3[p] = 0u;
                    if (kk) {
                        int bb = __ffs(kk) - 1; kk &= kk - 1;
                        const unsigned* R = V + (size_t)(c * 32 + bb) * VSTRIDE;
                        if (lane >= c)           q0[p] = __ldg(R + lane);
                        if (lane + 32 >= c)      q1[p] = __ldg(R + lane + 32);
                        if (lane + 64 >= c)      q2[p] = __ldg(R + lane + 64);
                        if (lane + 96 < NW)      q3[p] = __ldg(R + lane + 96);
                        pcnt++;
                    }
                }
                // overflow rows (rare): apply immediately
                while (kk) {
                    int bb = __ffs(kk) - 1; kk &= kk - 1;
                    const unsigned* R = V + (size_t)(c * 32 + bb) * VSTRIDE;
                    unsigned b0 = (lane >= c)      ? __ldg(R + lane)      : 0u;
                    unsigned b1 = (lane + 32 >= c) ? __ldg(R + lane + 32) : 0u;
                    unsigned b2 = (lane + 64 >= c) ? __ldg(R + lane + 64) : 0u;
                    unsigned b3 = (lane + 96 < NW) ? __ldg(R + lane + 96) : 0u;
                    if (b0) s_removed[lane] |= b0;
                    if (b1) s_removed[lane + 32] |= b1;
                    if (b2) s_removed[lane + 64] |= b2;
                    if (b3) s_removed[lane + 96] |= b3;
                }
            }

            diag = dn; specv = sn;
            __syncwarp();
        }
    }
    __syncthreads();

    // ---- scatter surviving scores into prob channel 20
    float* prob = out;
    for (int p = tid; p < NLOC; p += 256) {
        int o = g_sidx[base + p];
        float sc = g_ss[base + p];
        float v = (((s_kept[p >> 5] >> (p & 31)) & 1u)) ? sc : 0.0f;
        prob[((size_t)b * NLOC + o) * 21 + 20] = v;
    }
}

extern "C" void kernel_launch(void* const* d_in, const int* in_sizes, int n_in,
                              void* d_out, int out_size)
{
    (void)in_sizes; (void)n_in; (void)out_size;
    const float* x = (const float*)d_in[0];
    const float* im = (const float*)d_in[1];
    float* out = (float*)d_out;

    dim3 g1((NLOC + 127) / 128, BATCH);
    decode_kernel<<<g1, 128>>>(x, im, out);
    sort_kernel<<<BATCH, 1024>>>();
    dim3 g3(NW, 7, BATCH);
    mat_kernel<<<g3, 128>>>();
    reduce_kernel<<<BATCH, 256>>>(out);
}

// round 14
// speedup vs baseline: 4.3443x; 4.3443x over previous
#include <cuda_runtime.h>
#include <math.h>

#define NCLS 20
#define NA 5
#define HH 26
#define WW 26
#define NLOC 3380      // NA*HH*WW
#define NLOCP 3392     // padded stride for matC
#define NPAD 4096
#define NW 106         // ceil(NLOC/32)
#define BATCH 16
#define NMS_TH 0.45f
#define K2 0.31034482758f   // 0.45/1.45
#define PRE_TH 0.005f
#define FEAT_STRIDE 32.0f

__constant__ float c_biases[10] = {1.08f, 1.19f, 3.42f, 4.41f, 6.63f, 11.38f,
                                   9.42f, 5.11f, 16.62f, 10.52f};

// ---- device scratch (static; no allocations) ----
__device__ float g_x1[BATCH * NLOC], g_y1[BATCH * NLOC];
__device__ float g_x2[BATCH * NLOC], g_y2[BATCH * NLOC];
__device__ float g_ka[BATCH * NLOC], g_score[BATCH * NLOC];
__device__ float4 g_sbox[BATCH * NLOC];          // sorted (x1,y1,x2,y2)
__device__ float g_ska[BATCH * NLOC], g_ss[BATCH * NLOC];
__device__ int g_sidx[BATCH * NLOC];
__device__ unsigned g_alive[BATCH * NW];
// column-major suppression matrix: matC[b][w][j] = i-word w suppressor bits of row j
__device__ unsigned g_matC[(size_t)BATCH * NW * NLOCP];   // ~23 MB
// per-row bitmap of NONZERO suppressor words (128 bits, words 0..105)
__device__ unsigned g_rowmask[(size_t)BATCH * NLOCP * 4];

// ============ kernel 1: decode (fully parallel, fast-math transcendentals) ====
__global__ void decode_kernel(const float* __restrict__ x,
                              const float* __restrict__ im_info,
                              float* __restrict__ out)
{
    const int b = blockIdx.y;
    const int loc = blockIdx.x * 128 + threadIdx.x;
    if (loc >= NLOC) return;

    // zero this batch's rowmask entry for rank==loc (replay-safe re-init)
    *((uint4*)&g_rowmask[((size_t)(b * NLOCP + loc)) * 4]) = make_uint4(0u, 0u, 0u, 0u);

    const float im_h = im_info[0];
    const float im_w = im_info[1];
    const float netw = WW * FEAT_STRIDE;
    const float neth = HH * FEAT_STRIDE;
    const bool cond = (netw / im_w) < (neth / im_h);
    const float new_w = cond ? netw : im_w * neth / im_h;
    const float new_h = cond ? im_h * netw / im_w : neth;

    float* prob = out;
    float* bbox = out + (size_t)BATCH * NLOC * 21;
    const float* xb = x + (size_t)b * 125 * (HH * WW);

    int a = loc / (HH * WW);
    int rem = loc - a * (HH * WW);
    int hh = rem / WW;
    int ww = rem - hh * WW;

    float tx = xb[(2 * a) * 676 + rem];
    float ty = xb[(2 * a + 1) * 676 + rem];
    float tw = xb[(10 + 2 * a) * 676 + rem];
    float th = xb[(11 + 2 * a) * 676 + rem];
    float to = xb[(20 + a) * 676 + rem];

    float obj = 1.0f / (1.0f + __expf(-to));

    float cf[NCLS];
    float m = -INFINITY;
#pragma unroll
    for (int c = 0; c < NCLS; c++) {
        cf[c] = xb[(25 + 5 * c + a) * 676 + rem];
        m = fmaxf(m, cf[c]);
    }
    float sum = 0.0f;
#pragma unroll
    for (int c = 0; c < NCLS; c++) {
        cf[c] = __expf(cf[c] - m);
        sum += cf[c];
    }
    float inv = obj / sum;
    float* pr = prob + ((size_t)b * NLOC + loc) * 21;
#pragma unroll
    for (int c = 0; c < NCLS; c++) pr[c] = cf[c] * inv;

    float sx = 1.0f / (1.0f + __expf(-tx));
    float sy = 1.0f / (1.0f + __expf(-ty));
    float bxv = ((float)ww + sx) / (float)WW;
    float byv = ((float)hh + sy) / (float)HH;
    float bwv = c_biases[2 * a] * __expf(tw) / (float)WW;
    float bhv = c_biases[2 * a + 1] * __expf(th) / (float)HH;

    bxv = (bxv - (netw - new_w) * 0.5f / netw) / (new_w / netw);
    byv = (byv - (neth - new_h) * 0.5f / neth) / (new_h / neth);
    bwv = bwv * (netw / new_w);
    bhv = bhv * (neth / new_h);

    float cx = bxv * im_w, cy = byv * im_h;
    float bw2 = bwv * im_w, bh2 = bhv * im_h;

    float4* bo = (float4*)(bbox + ((size_t)b * NLOC + loc) * 4);
    *bo = make_float4(cx, cy, bw2, bh2);

    float X1 = cx - bw2 * 0.5f, Y1 = cy - bh2 * 0.5f;
    float X2 = cx + bw2 * 0.5f, Y2 = cy + bh2 * 0.5f;
    int gi = b * NLOC + loc;
    g_x1[gi] = X1; g_y1[gi] = Y1;
    g_x2[gi] = X2; g_y2[gi] = Y2;
    g_ka[gi] = K2 * ((X2 - X1) * (Y2 - Y1));
    g_score[gi] = (obj < PRE_TH) ? 0.0f : obj;
}

#define SWP(a, b) do { unsigned long long _t = (a); (a) = (b); (b) = _t; } while (0)

// ============ kernel 2: hybrid vectorized bitonic sort (64-bit packed keys) ====
// key = (float_bits(score) << 32) | (0xFFFFFFFF - idx); u64 desc == stable argsort(-s)
__global__ void __launch_bounds__(1024, 1)
sort_kernel()
{
    __shared__ __align__(16) unsigned long long skey[NPAD];
    ulonglong2* sk2 = (ulonglong2*)skey;
    const int b = blockIdx.x;
    const int tid = threadIdx.x;
    const int base = b * NLOC;

    for (int p = tid; p < NLOC; p += 1024) {
        unsigned sb = __float_as_uint(g_score[base + p]);
        skey[p] = ((unsigned long long)sb << 32) | (0xFFFFFFFFu - (unsigned)p);
    }
    for (int p = NLOC + tid; p < NPAD; p += 1024)
        skey[p] = 0ull;
    __syncthreads();

    for (unsigned k = 2; k <= NPAD; k <<= 1) {
        // phases j >= 4: duo-based (ulonglong2), 1024 duo-pairs, all threads active
        for (unsigned j = k >> 1; j >= 4; j >>= 1) {
            unsigned jd = j >> 1;
            unsigned t = (unsigned)tid;
            unsigned da = 2u * t - (t & (jd - 1u));
            unsigned db = da + jd;
            ulonglong2 A = sk2[da], B = sk2[db];
            bool dirDesc = (((2u * da) & k) == 0u);
            if ((B.x > A.x) == dirDesc) SWP(A.x, B.x);
            if ((B.y > A.y) == dirDesc) SWP(A.y, B.y);
            sk2[da] = A; sk2[db] = B;
            __syncthreads();
        }
        // fused tail: j=2 then j=1 in one unit (thread owns 4 consecutive elems)
        {
            unsigned g = (unsigned)tid;
            ulonglong2 d0 = sk2[2u * g], d1 = sk2[2u * g + 1u];
            if (k >= 4u) {
                bool dir = (((4u * g) & k) == 0u);
                if ((d1.x > d0.x) == dir) SWP(d0.x, d1.x);   // j=2
                if ((d1.y > d0.y) == dir) SWP(d0.y, d1.y);
                if ((d0.y > d0.x) == dir) SWP(d0.x, d0.y);   // j=1
                if ((d1.y > d1.x) == dir) SWP(d1.x, d1.y);
            } else {  // k == 2: pair (4g,4g+1) desc, (4g+2,4g+3) asc
                if (d0.y > d0.x) SWP(d0.x, d0.y);
                if (!(d1.y > d1.x)) SWP(d1.x, d1.y);
            }
            sk2[2u * g] = d0; sk2[2u * g + 1u] = d1;
            __syncthreads();
        }
    }

    for (int p = tid; p < NLOC; p += 1024) {
        unsigned long long key = skey[p];
        float sc = __uint_as_float((unsigned)(key >> 32));
        int o = (int)(0xFFFFFFFFu - (unsigned)key);
        g_ss[base + p] = sc;
        g_sidx[base + p] = o;
        g_sbox[base + p] = make_float4(g_x1[base + o], g_y1[base + o],
                                       g_x2[base + o], g_y2[base + o]);
        // dead boxes can never suppress: ka = +INF makes inter > kai+kaj false
        g_ska[base + p] = (sc > 0.0f) ? g_ka[base + o] : INFINITY;
    }
    __syncthreads();
    for (int chunk = 0; chunk < NPAD; chunk += 1024) {
        int p = chunk + tid;
        bool alive = (p < NLOC) && ((skey[p] >> 32) != 0ull);
        unsigned w = __ballot_sync(0xFFFFFFFFu, alive);
        int word = p >> 5;
        if ((tid & 31) == 0 && word < NW)
            g_alive[b * NW + word] = w;
    }
}

// ============ kernel 3: suppression matrix + per-row live-word bitmap ==========
__global__ void __launch_bounds__(128, 8)
mat_kernel()
{
    const int w = blockIdx.x;                       // i-word
    const int b = blockIdx.z;
    const int lane = threadIdx.x & 31;
    const int warpid = threadIdx.x >> 5;
    const int jword = blockIdx.y * 4 + warpid;      // j-word
    if (jword < w || jword >= NW) return;

    const int base = b * NLOC;
    const int i = w * 32 + lane;
    float4 ibx = make_float4(0.f, 0.f, 0.f, 0.f);
    float ika = INFINITY;
    if (i < NLOC) { ibx = g_sbox[base + i]; ika = g_ska[base + i]; }

    unsigned myword = 0u;
    const int jbase = jword * 32;

#pragma unroll 4
    for (int r = 0; r < 32; r++) {
        int j = jbase + r;
        if (j >= NLOC) break;                        // uniform
        float4 jb = __ldg(&g_sbox[base + j]);
        float jka = __ldg(&g_ska[base + j]);
        float iw = fminf(ibx.z, jb.z) - fmaxf(ibx.x, jb.x);
        float ih = fminf(ibx.w, jb.w) - fmaxf(ibx.y, jb.y);
        float inter = fmaxf(iw, 0.0f) * fmaxf(ih, 0.0f);
        bool sup = (inter > ika + jka) && (j > i);
        unsigned m = __ballot_sync(0xFFFFFFFFu, sup);
        if (lane == r) myword = m;
    }

    int j = jbase + lane;
    g_matC[((size_t)(b * NW + w)) * NLOCP + j] = myword;
    if (myword && j < NLOC)
        atomicOr(&g_rowmask[((size_t)(b * NLOCP + j)) * 4 + (w >> 5)],
                 1u << (w & 31));
}

// pop lowest live word from 128-bit bitmap held in two u64 regs
#define POPW(A, Bm, wvar) \
    do { if (A) { wvar = __ffsll(A) - 1; A &= A - 1; } \
         else   { wvar = 64 + __ffsll(Bm) - 1; Bm &= Bm - 1; } } while (0)

// ============ kernel 4: bit-level fixpoint — check ALL cached words per round ==
__global__ void __launch_bounds__(1024, 1)
reduce_kernel(float* __restrict__ out)
{
    __shared__ unsigned kept[NW];
    __shared__ unsigned removed[NW];
    __shared__ int chg[3];

    const int b = blockIdx.x;
    const int tid = threadIdx.x;
    const int base = b * NLOC;
    const unsigned* M = g_matC + (size_t)b * NW * NLOCP;   // M[w*NLOCP + j]

    for (int w = tid; w < NW; w += 1024) {
        kept[w] = 0u;
        removed[w] = ~g_alive[b * NW + w];   // dead boxes start removed
    }
    if (tid < 3) chg[tid] = 0;
    __syncthreads();

    unsigned v0[4], v1[4], v2[4], wpk[4];
    int pend[4];
    bool det[4];
    unsigned long long rmA[4], rmB[4];

    // ---- init: prefetch up to 3 live words with INDEPENDENT loads
#pragma unroll
    for (int k = 0; k < 4; k++) {
        int j = tid + k * 1024;
        det[k] = true; pend[k] = 0; wpk[k] = 0;
        v0[k] = v1[k] = v2[k] = 0u;
        rmA[k] = 0ull; rmB[k] = 0ull;
        if (j >= NLOC) continue;
        if ((removed[j >> 5] >> (j & 31)) & 1u) continue;     // dead -> done
        uint4 rv = *((const uint4*)&g_rowmask[((size_t)(b * NLOCP + j)) * 4]);
        unsigned long long A  = (unsigned long long)rv.x | ((unsigned long long)rv.y << 32);
        unsigned long long Bm = (unsigned long long)rv.z | ((unsigned long long)rv.w << 32);
        int w0 = 0, w1 = 0, w2 = 0, cnt = 0;
        if (A | Bm) { POPW(A, Bm, w0); cnt = 1;
            if (A | Bm) { POPW(A, Bm, w1); cnt = 2;
                if (A | Bm) { POPW(A, Bm, w2); cnt = 3; } } }
        if (cnt == 0) { atomicOr(&kept[j >> 5], 1u << (j & 31)); continue; }
        v0[k] = __ldg(M + (size_t)w0 * NLOCP + j);
        if (cnt > 1) v1[k] = __ldg(M + (size_t)w1 * NLOCP + j);
        if (cnt > 2) v2[k] = __ldg(M + (size_t)w2 * NLOCP + j);
        wpk[k] = (unsigned)w0 | ((unsigned)w1 << 8) | ((unsigned)w2 << 16);
        rmA[k] = A; rmB[k] = Bm;
        pend[k] = (1 << cnt) - 1;
        det[k] = false;
    }
    __syncthreads();

    // ---- rounds: monotone lattice -> stale reads safe; ONE barrier per round.
    int r = 0;
    while (true) {
        const int slot = r - (r / 3) * 3;
        int next = slot + 1; if (next == 3) next = 0;

#pragma unroll
        for (int k = 0; k < 4; k++) {
            if (det[k]) continue;
            int j = tid + k * 1024;
            unsigned wp = wpk[k];
            int p = pend[k];
            bool dec = false;

            if (p & 1) {
                int w = wp & 0xFF;
                if (v0[k] & kept[w]) {
                    atomicOr(&removed[j >> 5], 1u << (j & 31)); dec = true;
                } else if (!(v0[k] & ~removed[w])) p &= ~1;
            }
            if (!dec && (p & 2)) {
                int w = (wp >> 8) & 0xFF;
                if (v1[k] & kept[w]) {
                    atomicOr(&removed[j >> 5], 1u << (j & 31)); dec = true;
                } else if (!(v1[k] & ~removed[w])) p &= ~2;
            }
            if (!dec && (p & 4)) {
                int w = (wp >> 16) & 0xFF;
                if (v2[k] & kept[w]) {
                    atomicOr(&removed[j >> 5], 1u << (j & 31)); dec = true;
                } else if (!(v2[k] & ~removed[w])) p &= ~4;
            }

            if (!dec && p == 0) {
                for (;;) {
                    if (!(rmA[k] | rmB[k])) {
                        atomicOr(&kept[j >> 5], 1u << (j & 31));
                        dec = true; break;
                    }
                    int w3; POPW(rmA[k], rmB[k], w3);
                    unsigned v3 = __ldg(M + (size_t)w3 * NLOCP + j);
                    if (v3 & kept[w3]) {
                        atomicOr(&removed[j >> 5], 1u << (j & 31));
                        dec = true; break;
                    }
                    if (v3 & ~removed[w3]) {       // live again: park in slot 0
                        v0[k] = v3;
                        wpk[k] = (wp & 0xFFFFFF00u) | (unsigned)w3;
                        p = 1; break;
                    }
                }
            }

            if (dec) { det[k] = true; chg[slot] = 1; }
            else if (p != pend[k]) { pend[k] = p; chg[slot] = 1; }
        }
        if (tid == 0) chg[next] = 0;
        __syncthreads();
        if (!chg[slot]) break;
        r++;
    }

    // ---- scatter surviving scores into prob channel 20
    float* prob = out;
    for (int p = tid; p < NLOC; p += 1024) {
        int o = g_sidx[base + p];
        float sc = g_ss[base + p];
        float v = (sc > 0.0f && ((kept[p >> 5] >> (p & 31)) & 1u)) ? sc : 0.0f;
        prob[((size_t)b * NLOC + o) * 21 + 20] = v;
    }
}

extern "C" void kernel_launch(void* const* d_in, const int* in_sizes, int n_in,
                              void* d_out, int out_size)
{
    (void)in_sizes; (void)n_in; (void)out_size;
    const float* x = (const float*)d_in[0];
    const float* im = (const float*)d_in[1];
    float* out = (float*)d_out;

    dim3 g1((NLOC + 127) / 128, BATCH);
    decode_kernel<<<g1, 128>>>(x, im, out);
    sort_kernel<<<BATCH, 1024>>>();
    dim3 g3(NW, (NW + 3) / 4, BATCH);
    mat_kernel<<<g3, 128>>>();
    reduce_kernel<<<BATCH, 1024>>>(out);
}

// round 15
// speedup vs baseline: 4.5258x; 1.0418x over previous
#include <cuda_runtime.h>
#include <math.h>

#define NCLS 20
#define NA 5
#define HH 26
#define WW 26
#define NLOC 3380      // NA*HH*WW
#define NLOCP 3392     // padded stride for matC
#define NPAD 4096
#define NW 106         // ceil(NLOC/32)
#define BATCH 16
#define NMS_TH 0.45f
#define K2 0.31034482758f   // 0.45/1.45
#define PRE_TH 0.005f
#define FEAT_STRIDE 32.0f

__constant__ float c_biases[10] = {1.08f, 1.19f, 3.42f, 4.41f, 6.63f, 11.38f,
                                   9.42f, 5.11f, 16.62f, 10.52f};

// ---- device scratch (static; no allocations) ----
__device__ float g_x1[BATCH * NLOC], g_y1[BATCH * NLOC];
__device__ float g_x2[BATCH * NLOC], g_y2[BATCH * NLOC];
__device__ float g_ka[BATCH * NLOC], g_score[BATCH * NLOC];
__device__ float4 g_sbox[BATCH * NLOC];          // sorted (x1,y1,x2,y2)
__device__ float g_ska[BATCH * NLOC], g_ss[BATCH * NLOC];
__device__ int g_sidx[BATCH * NLOC];
__device__ unsigned g_alive[BATCH * NW];
// column-major suppression matrix: matC[b][w][j] = i-word w suppressor bits of row j
__device__ unsigned g_matC[(size_t)BATCH * NW * NLOCP];   // ~23 MB
// per-row bitmap of NONZERO suppressor words (128 bits, words 0..105)
__device__ unsigned g_rowmask[(size_t)BATCH * NLOCP * 4];

// ============ kernel 1: decode (fully parallel, fast-math transcendentals) ====
__global__ void decode_kernel(const float* __restrict__ x,
                              const float* __restrict__ im_info,
                              float* __restrict__ out)
{
    const int b = blockIdx.y;
    const int loc = blockIdx.x * 128 + threadIdx.x;
    if (loc >= NLOC) return;

    // zero this batch's rowmask entry for rank==loc (replay-safe re-init)
    *((uint4*)&g_rowmask[((size_t)(b * NLOCP + loc)) * 4]) = make_uint4(0u, 0u, 0u, 0u);

    const float im_h = im_info[0];
    const float im_w = im_info[1];
    const float netw = WW * FEAT_STRIDE;
    const float neth = HH * FEAT_STRIDE;
    const bool cond = (netw / im_w) < (neth / im_h);
    const float new_w = cond ? netw : im_w * neth / im_h;
    const float new_h = cond ? im_h * netw / im_w : neth;

    float* prob = out;
    float* bbox = out + (size_t)BATCH * NLOC * 21;
    const float* xb = x + (size_t)b * 125 * (HH * WW);

    int a = loc / (HH * WW);
    int rem = loc - a * (HH * WW);
    int hh = rem / WW;
    int ww = rem - hh * WW;

    float tx = xb[(2 * a) * 676 + rem];
    float ty = xb[(2 * a + 1) * 676 + rem];
    float tw = xb[(10 + 2 * a) * 676 + rem];
    float th = xb[(11 + 2 * a) * 676 + rem];
    float to = xb[(20 + a) * 676 + rem];

    float obj = 1.0f / (1.0f + __expf(-to));

    float cf[NCLS];
    float m = -INFINITY;
#pragma unroll
    for (int c = 0; c < NCLS; c++) {
        cf[c] = xb[(25 + 5 * c + a) * 676 + rem];
        m = fmaxf(m, cf[c]);
    }
    float sum = 0.0f;
#pragma unroll
    for (int c = 0; c < NCLS; c++) {
        cf[c] = __expf(cf[c] - m);
        sum += cf[c];
    }
    float inv = obj / sum;
    float* pr = prob + ((size_t)b * NLOC + loc) * 21;
#pragma unroll
    for (int c = 0; c < NCLS; c++) pr[c] = cf[c] * inv;

    float sx = 1.0f / (1.0f + __expf(-tx));
    float sy = 1.0f / (1.0f + __expf(-ty));
    float bxv = ((float)ww + sx) / (float)WW;
    float byv = ((float)hh + sy) / (float)HH;
    float bwv = c_biases[2 * a] * __expf(tw) / (float)WW;
    float bhv = c_biases[2 * a + 1] * __expf(th) / (float)HH;

    bxv = (bxv - (netw - new_w) * 0.5f / netw) / (new_w / netw);
    byv = (byv - (neth - new_h) * 0.5f / neth) / (new_h / neth);
    bwv = bwv * (netw / new_w);
    bhv = bhv * (neth / new_h);

    float cx = bxv * im_w, cy = byv * im_h;
    float bw2 = bwv * im_w, bh2 = bhv * im_h;

    float4* bo = (float4*)(bbox + ((size_t)b * NLOC + loc) * 4);
    *bo = make_float4(cx, cy, bw2, bh2);

    float X1 = cx - bw2 * 0.5f, Y1 = cy - bh2 * 0.5f;
    float X2 = cx + bw2 * 0.5f, Y2 = cy + bh2 * 0.5f;
    int gi = b * NLOC + loc;
    g_x1[gi] = X1; g_y1[gi] = Y1;
    g_x2[gi] = X2; g_y2[gi] = Y2;
    g_ka[gi] = K2 * ((X2 - X1) * (Y2 - Y1));
    g_score[gi] = (obj < PRE_TH) ? 0.0f : obj;
}

#define SWP(a, b) do { unsigned long long _t = (a); (a) = (b); (b) = _t; } while (0)

// ============ kernel 2: hybrid vectorized bitonic sort (64-bit packed keys) ====
// key = (float_bits(score) << 32) | (0xFFFFFFFF - idx); u64 desc == stable argsort(-s)
__global__ void __launch_bounds__(1024, 1)
sort_kernel()
{
    __shared__ __align__(16) unsigned long long skey[NPAD];
    ulonglong2* sk2 = (ulonglong2*)skey;
    const int b = blockIdx.x;
    const int tid = threadIdx.x;
    const int base = b * NLOC;

    for (int p = tid; p < NLOC; p += 1024) {
        unsigned sb = __float_as_uint(g_score[base + p]);
        skey[p] = ((unsigned long long)sb << 32) | (0xFFFFFFFFu - (unsigned)p);
    }
    for (int p = NLOC + tid; p < NPAD; p += 1024)
        skey[p] = 0ull;
    __syncthreads();

    for (unsigned k = 2; k <= NPAD; k <<= 1) {
        // phases j >= 4: duo-based (ulonglong2), 1024 duo-pairs, all threads active
        for (unsigned j = k >> 1; j >= 4; j >>= 1) {
            unsigned jd = j >> 1;
            unsigned t = (unsigned)tid;
            unsigned da = 2u * t - (t & (jd - 1u));
            unsigned db = da + jd;
            ulonglong2 A = sk2[da], B = sk2[db];
            bool dirDesc = (((2u * da) & k) == 0u);
            if ((B.x > A.x) == dirDesc) SWP(A.x, B.x);
            if ((B.y > A.y) == dirDesc) SWP(A.y, B.y);
            sk2[da] = A; sk2[db] = B;
            __syncthreads();
        }
        // fused tail: j=2 then j=1 in one unit (thread owns 4 consecutive elems)
        {
            unsigned g = (unsigned)tid;
            ulonglong2 d0 = sk2[2u * g], d1 = sk2[2u * g + 1u];
            if (k >= 4u) {
                bool dir = (((4u * g) & k) == 0u);
                if ((d1.x > d0.x) == dir) SWP(d0.x, d1.x);   // j=2
                if ((d1.y > d0.y) == dir) SWP(d0.y, d1.y);
                if ((d0.y > d0.x) == dir) SWP(d0.x, d0.y);   // j=1
                if ((d1.y > d1.x) == dir) SWP(d1.x, d1.y);
            } else {  // k == 2: pair (4g,4g+1) desc, (4g+2,4g+3) asc
                if (d0.y > d0.x) SWP(d0.x, d0.y);
                if (!(d1.y > d1.x)) SWP(d1.x, d1.y);
            }
            sk2[2u * g] = d0; sk2[2u * g + 1u] = d1;
            __syncthreads();
        }
    }

    for (int p = tid; p < NLOC; p += 1024) {
        unsigned long long key = skey[p];
        float sc = __uint_as_float((unsigned)(key >> 32));
        int o = (int)(0xFFFFFFFFu - (unsigned)key);
        g_ss[base + p] = sc;
        g_sidx[base + p] = o;
        g_sbox[base + p] = make_float4(g_x1[base + o], g_y1[base + o],
                                       g_x2[base + o], g_y2[base + o]);
        // dead boxes can never suppress: ka = +INF makes inter > kai+kaj false
        g_ska[base + p] = (sc > 0.0f) ? g_ka[base + o] : INFINITY;
    }
    __syncthreads();
    for (int chunk = 0; chunk < NPAD; chunk += 1024) {
        int p = chunk + tid;
        bool alive = (p < NLOC) && ((skey[p] >> 32) != 0ull);
        unsigned w = __ballot_sync(0xFFFFFFFFu, alive);
        int word = p >> 5;
        if ((tid & 31) == 0 && word < NW)
            g_alive[b * NW + word] = w;
    }
}

// ============ kernel 3: suppression matrix + per-row live-word bitmap ==========
__global__ void __launch_bounds__(128, 8)
mat_kernel()
{
    const int w = blockIdx.x;                       // i-word
    const int b = blockIdx.z;
    const int lane = threadIdx.x & 31;
    const int warpid = threadIdx.x >> 5;
    const int jword = blockIdx.y * 4 + warpid;      // j-word
    if (jword < w || jword >= NW) return;

    const int base = b * NLOC;
    const int i = w * 32 + lane;
    float4 ibx = make_float4(0.f, 0.f, 0.f, 0.f);
    float ika = INFINITY;
    if (i < NLOC) { ibx = g_sbox[base + i]; ika = g_ska[base + i]; }

    unsigned myword = 0u;
    const int jbase = jword * 32;

#pragma unroll 4
    for (int r = 0; r < 32; r++) {
        int j = jbase + r;
        if (j >= NLOC) break;                        // uniform
        float4 jb = __ldg(&g_sbox[base + j]);
        float jka = __ldg(&g_ska[base + j]);
        float iw = fminf(ibx.z, jb.z) - fmaxf(ibx.x, jb.x);
        float ih = fminf(ibx.w, jb.w) - fmaxf(ibx.y, jb.y);
        float inter = fmaxf(iw, 0.0f) * fmaxf(ih, 0.0f);
        bool sup = (inter > ika + jka) && (j > i);
        unsigned m = __ballot_sync(0xFFFFFFFFu, sup);
        if (lane == r) myword = m;
    }

    int j = jbase + lane;
    g_matC[((size_t)(b * NW + w)) * NLOCP + j] = myword;
    if (myword && j < NLOC)
        atomicOr(&g_rowmask[((size_t)(b * NLOCP + j)) * 4 + (w >> 5)],
                 1u << (w & 31));
}

// pop lowest live word from 128-bit bitmap held in two u64 regs
#define POPW(A, Bm, wvar) \
    do { if (A) { wvar = __ffsll(A) - 1; A &= A - 1; } \
         else   { wvar = 64 + __ffsll(Bm) - 1; Bm &= Bm - 1; } } while (0)

// ============ kernel 4: barrier-free asynchronous monotone fixpoint ============
// kept/removed bits only go 0->1; shared atomics are block-coherent; each thread
// spins until ITS rows are determined, then parks at one final barrier.
__global__ void __launch_bounds__(1024, 1)
reduce_kernel(float* __restrict__ out)
{
    __shared__ unsigned kept[NW];
    __shared__ unsigned removed[NW];

    const int b = blockIdx.x;
    const int tid = threadIdx.x;
    const int base = b * NLOC;
    const unsigned* M = g_matC + (size_t)b * NW * NLOCP;   // M[w*NLOCP + j]

    volatile unsigned* vkept = kept;
    volatile unsigned* vrem  = removed;

    for (int w = tid; w < NW; w += 1024) {
        kept[w] = 0u;
        removed[w] = ~g_alive[b * NW + w];   // dead boxes start removed
    }
    __syncthreads();

    unsigned v0[4], v1[4], v2[4], wpk[4];
    int pend[4];
    bool det[4];
    unsigned long long rmA[4], rmB[4];
    int undet = 0;

    // ---- init: prefetch up to 3 live words with INDEPENDENT loads
#pragma unroll
    for (int k = 0; k < 4; k++) {
        int j = tid + k * 1024;
        det[k] = true; pend[k] = 0; wpk[k] = 0;
        v0[k] = v1[k] = v2[k] = 0u;
        rmA[k] = 0ull; rmB[k] = 0ull;
        if (j >= NLOC) continue;
        if ((removed[j >> 5] >> (j & 31)) & 1u) continue;     // dead -> done
        uint4 rv = *((const uint4*)&g_rowmask[((size_t)(b * NLOCP + j)) * 4]);
        unsigned long long A  = (unsigned long long)rv.x | ((unsigned long long)rv.y << 32);
        unsigned long long Bm = (unsigned long long)rv.z | ((unsigned long long)rv.w << 32);
        int w0 = 0, w1 = 0, w2 = 0, cnt = 0;
        if (A | Bm) { POPW(A, Bm, w0); cnt = 1;
            if (A | Bm) { POPW(A, Bm, w1); cnt = 2;
                if (A | Bm) { POPW(A, Bm, w2); cnt = 3; } } }
        if (cnt == 0) { atomicOr(&kept[j >> 5], 1u << (j & 31)); continue; }
        v0[k] = __ldg(M + (size_t)w0 * NLOCP + j);
        if (cnt > 1) v1[k] = __ldg(M + (size_t)w1 * NLOCP + j);
        if (cnt > 2) v2[k] = __ldg(M + (size_t)w2 * NLOCP + j);
        wpk[k] = (unsigned)w0 | ((unsigned)w1 << 8) | ((unsigned)w2 << 16);
        rmA[k] = A; rmB[k] = Bm;
        pend[k] = (1 << cnt) - 1;
        det[k] = false;
        undet++;
    }

    // ---- asynchronous spin: no barriers; monotone state makes stale reads safe
    while (undet > 0) {
#pragma unroll
        for (int k = 0; k < 4; k++) {
            if (det[k]) continue;
            int j = tid + k * 1024;
            unsigned wp = wpk[k];
            int p = pend[k];
            bool dec = false;

            if (p & 1) {
                int w = wp & 0xFF;
                if (v0[k] & vkept[w]) {
                    atomicOr(&removed[j >> 5], 1u << (j & 31)); dec = true;
                } else if (!(v0[k] & ~vrem[w])) p &= ~1;
            }
            if (!dec && (p & 2)) {
                int w = (wp >> 8) & 0xFF;
                if (v1[k] & vkept[w]) {
                    atomicOr(&removed[j >> 5], 1u << (j & 31)); dec = true;
                } else if (!(v1[k] & ~vrem[w])) p &= ~2;
            }
            if (!dec && (p & 4)) {
                int w = (wp >> 16) & 0xFF;
                if (v2[k] & vkept[w]) {
                    atomicOr(&removed[j >> 5], 1u << (j & 31)); dec = true;
                } else if (!(v2[k] & ~vrem[w])) p &= ~4;
            }

            if (!dec && p == 0) {
                // drain overflow bitmap (rare: rows with >3 live words)
                for (;;) {
                    if (!(rmA[k] | rmB[k])) {
                        atomicOr(&kept[j >> 5], 1u << (j & 31));
                        dec = true; break;
                    }
                    int w3; POPW(rmA[k], rmB[k], w3);
                    unsigned v3 = __ldg(M + (size_t)w3 * NLOCP + j);
                    if (v3 & vkept[w3]) {
                        atomicOr(&removed[j >> 5], 1u << (j & 31));
                        dec = true; break;
                    }
                    if (v3 & ~vrem[w3]) {          // live again: park in slot 0
                        v0[k] = v3;
                        wpk[k] = (wp & 0xFFFFFF00u) | (unsigned)w3;
                        p = 1; break;
                    }
                }
            }

            if (dec) { det[k] = true; undet--; }
            else pend[k] = p;
        }
    }
    __syncthreads();

    // ---- scatter surviving scores into prob channel 20
    float* prob = out;
    for (int p = tid; p < NLOC; p += 1024) {
        int o = g_sidx[base + p];
        float sc = g_ss[base + p];
        float v = (sc > 0.0f && ((kept[p >> 5] >> (p & 31)) & 1u)) ? sc : 0.0f;
        prob[((size_t)b * NLOC + o) * 21 + 20] = v;
    }
}

extern "C" void kernel_launch(void* const* d_in, const int* in_sizes, int n_in,
                              void* d_out, int out_size)
{
    (void)in_sizes; (void)n_in; (void)out_size;
    const float* x = (const float*)d_in[0];
    const float* im = (const float*)d_in[1];
    float* out = (float*)d_out;

    dim3 g1((NLOC + 127) / 128, BATCH);
    decode_kernel<<<g1, 128>>>(x, im, out);
    sort_kernel<<<BATCH, 1024>>>();
    dim3 g3(NW, (NW + 3) / 4, BATCH);
    mat_kernel<<<g3, 128>>>();
    reduce_kernel<<<BATCH, 1024>>>(out);
}